// round 14
// baseline (speedup 1.0000x reference)
#include <cuda_runtime.h>
#include <math.h>

// Problem constants
#define DIN   256      // agent input dim
#define C6    192      // S*6 = 32*6
#define CAN   128      // canvas size
#define NT    50       // samples per curve
#define NPTS  (32*NT)  // 1600 curve points per image
#define HDIM  129      // center coords are in [0,128]
#define HROW  68       // u32 words per H row (129 u16 slots, padded to 16B multiple)
#define HPWORDS (HDIM*HROW)   // 8772 (multiple of 4)
#define SMEM_PAINT (HPWORDS * 4)   // 35088 B -> 6 blocks/SM

// ---------------------------------------------------------------------------
// f32x2 packed helpers (bit-identical per-lane IEEE fp32 ops)
// ---------------------------------------------------------------------------
__device__ __forceinline__ void ffma2(unsigned long long& d,
                                      unsigned long long a,
                                      unsigned long long b) {
    asm("fma.rn.f32x2 %0, %1, %2, %0;" : "+l"(d) : "l"(a), "l"(b));
}
__device__ __forceinline__ void fadd2(unsigned long long& d,
                                      unsigned long long a) {
    asm("add.rn.f32x2 %0, %0, %1;" : "+l"(d) : "l"(a));
}
__device__ __forceinline__ unsigned long long pack2(float lo, float hi) {
    unsigned long long r;
    asm("mov.b64 %0, {%1, %2};" : "=l"(r) : "f"(lo), "f"(hi));
    return r;
}
__device__ __forceinline__ void unpack2(unsigned long long v, float& lo, float& hi) {
    asm("mov.b64 {%0, %1}, %2;" : "=f"(lo), "=f"(hi) : "l"(v));
}

// ---------------------------------------------------------------------------
// Kernel A: mu = x@W + b ; sample = sigmoid(mu).  R9/R11 mapping (q = tid%48,
// p = (tid/48)&3, g = tid/192).  ONLY change vs R11: the k-loop is software-
// pipelined with a double-buffered W prefetch, so the next 8 LDG.128 are in
// flight while the current 8 FFMA2 batches execute (T_CTA shrinks; FP order
// unchanged).
// ---------------------------------------------------------------------------
#define RPB 8
#define AGENT_THREADS 768
#define KSPLIT 4
#define KCHUNK (DIN / KSPLIT)    // 64
#define XSTR 10                  // xs row stride in floats (even -> u64-aligned)

__global__ void __launch_bounds__(AGENT_THREADS) agent_kernel(
    const float* __restrict__ x,
    const float* __restrict__ W,
    const float* __restrict__ bvec,
    float* __restrict__ out,   // full output buffer
    int B)
{
    __shared__ float xs[DIN * XSTR];                     // [k][r], stride 10
    __shared__ unsigned long long part[C6 * (KSPLIT-1) * 4]; // 2304 u64 = 18KB

    const int tid  = threadIdx.x;
    const int q    = tid % 48;            // column quad: cols 4q..4q+3
    const int p    = (tid / 48) & 3;      // rowpair: rows 2p, 2p+1
    const int g    = tid / 192;           // k-group: k in [64g, 64g+64)
    const int row0 = blockIdx.x * RPB;

    for (int idx = tid; idx < RPB * DIN; idx += AGENT_THREADS) {
        int r = idx >> 8;        // 0..7
        int k = idx & 255;
        xs[k * XSTR + r] = x[(size_t)(row0 + r) * DIN + k];
    }
    __syncthreads();

    unsigned long long acc0, acc1, acc2, acc3;
    if (g == 0) {
        float4 b4 = *(const float4*)&bvec[q * 4];
        acc0 = pack2(b4.x, b4.x);
        acc1 = pack2(b4.y, b4.y);
        acc2 = pack2(b4.z, b4.z);
        acc3 = pack2(b4.w, b4.w);
    } else {
        acc0 = acc1 = acc2 = acc3 = 0ull;
    }

    const float4* Wq = (const float4*)(W + q * 4);   // row stride 48 float4s
    const float*  xp = &xs[p * 2];
    const int     kb = g * KCHUNK;

    // software-pipelined k-loop: double-buffered 8-deep W prefetch
    float4 wv[8], wn[8];
#pragma unroll
    for (int u = 0; u < 8; ++u)
        wv[u] = __ldg(&Wq[(size_t)(kb + u) * 48]);

#pragma unroll 1
    for (int k0 = 0; k0 < KCHUNK; k0 += 8) {
        if (k0 + 8 < KCHUNK) {
#pragma unroll
            for (int u = 0; u < 8; ++u)
                wn[u] = __ldg(&Wq[(size_t)(kb + k0 + 8 + u) * 48]);  // prefetch
        }
#pragma unroll
        for (int u = 0; u < 8; ++u) {
            unsigned long long v =
                *(const unsigned long long*)&xp[(kb + k0 + u) * XSTR];
            ffma2(acc0, v, pack2(wv[u].x, wv[u].x));
            ffma2(acc1, v, pack2(wv[u].y, wv[u].y));
            ffma2(acc2, v, pack2(wv[u].z, wv[u].z));
            ffma2(acc3, v, pack2(wv[u].w, wv[u].w));
        }
#pragma unroll
        for (int u = 0; u < 8; ++u) wv[u] = wn[u];
    }

    const int slot = (p * 48 + q) * ((KSPLIT - 1) * 4);
    if (g > 0) {
        unsigned long long* pj = &part[slot + (g - 1) * 4];
        pj[0] = acc0; pj[1] = acc1; pj[2] = acc2; pj[3] = acc3;
    }
    __syncthreads();

    if (g == 0) {
        const unsigned long long* pj = &part[slot];
#pragma unroll
        for (int gg = 0; gg < KSPLIT - 1; ++gg) {
            fadd2(acc0, pj[gg * 4 + 0]);
            fadd2(acc1, pj[gg * 4 + 1]);
            fadd2(acc2, pj[gg * 4 + 2]);
            fadd2(acc3, pj[gg * 4 + 3]);
        }

        // Output layout: [sketch B*128*128][log_prob B][entropy B][sample B*192]
        const size_t off_lp  = (size_t)B * (CAN * CAN);
        const size_t off_ent = off_lp + B;
        const size_t off_smp = off_ent + B;

        // log_prob / entropy are constants (raw == mu).
        const float logscale = logf(1e-4f);
        const float l2pi     = logf(6.2831855f);       // log(fl32(2*pi))
        const float lp  = 192.0f * (-logscale - 0.5f * l2pi);
        const float ent = 192.0f * (0.5f + 0.5f * l2pi + logscale);
        if (tid < RPB) {
            out[off_lp  + row0 + tid] = lp;
            out[off_ent + row0 + tid] = ent;
        }

        float m0x, m1x, m0y, m1y, m0z, m1z, m0w, m1w;
        unpack2(acc0, m0x, m1x);   // col 4q+0: rows 2p, 2p+1
        unpack2(acc1, m0y, m1y);
        unpack2(acc2, m0z, m1z);
        unpack2(acc3, m0w, m1w);

        float4 s0, s1;
        s0.x = 1.0f / (1.0f + expf(-m0x));
        s0.y = 1.0f / (1.0f + expf(-m0y));
        s0.z = 1.0f / (1.0f + expf(-m0z));
        s0.w = 1.0f / (1.0f + expf(-m0w));
        s1.x = 1.0f / (1.0f + expf(-m1x));
        s1.y = 1.0f / (1.0f + expf(-m1y));
        s1.z = 1.0f / (1.0f + expf(-m1z));
        s1.w = 1.0f / (1.0f + expf(-m1w));

        float* smp = out + off_smp;
        *(float4*)&smp[(size_t)(row0 + 2 * p    ) * C6 + q * 4] = s0;
        *(float4*)&smp[(size_t)(row0 + 2 * p + 1) * C6 + q * 4] = s1;
    }
}

// ---------------------------------------------------------------------------
// Kernel B: paint — EXACT R11 version (35.2 us proven).
//  1) histogram with run-length merged atomics (scalar __fmul_rn/__fadd_rn
//     curve eval, bit-identical to reference)
//  2) pass A (y-window): IN PLACE, one WARP per row, shuffles for neighbors
//  3) pass B (x-window): register-rolling over px, inline clip arithmetic
// Edge weights from clipping:  p=0 -> {2,1} on centers {0,1};
//                              p=127 -> {1,2,3} on centers {126,127,128}.
// All packed-u16 sums bounded by 14400 < 65536: no carry across halves.
// ---------------------------------------------------------------------------
__global__ void __launch_bounds__(256) paint_kernel(
    const float* __restrict__ sample,   // [B, 192]
    float* __restrict__ sketch)         // [B, 128, 128]
{
    extern __shared__ uint4 sh16[];       // 16B-aligned base
    unsigned int* Hp = (unsigned int*)sh16;   // [129][68] u32
    __shared__ float prm[C6];

    const int b   = blockIdx.x;
    const int tid = threadIdx.x;

    // zero Hp with 16B stores
    {
        uint4 z = make_uint4(0u, 0u, 0u, 0u);
        uint4* hp4 = (uint4*)Hp;
        for (int i = tid; i < HPWORDS / 4; i += 256) hp4[i] = z;
    }
    if (tid < C6) prm[tid] = __fmul_rn(sample[(size_t)b * C6 + tid], 128.0f);
    __syncthreads();

    // ---- histogram: run-length merged atomics ----
    // thread = (spline s = tid>>3, chunk sub = tid&7); sample counts
    // {7,7,6,6,6,6,6,6} -> start 0,7,14,20,26,32,38,44.
    {
        const int s    = tid >> 3;
        const int sub  = tid & 7;
        const int st   = (sub < 2) ? 7 * sub : 14 + 6 * (sub - 2);
        const int cnt  = (sub < 2) ? 7 : 6;

        const float q0 = prm[s * 6 + 0];
        const float q1 = prm[s * 6 + 1];
        const float q2 = prm[s * 6 + 2];
        const float q3 = prm[s * 6 + 3];
        const float q4 = prm[s * 6 + 4];
        const float q5 = prm[s * 6 + 5];

        const float dt = 1.0f / 49.0f;   // fl32((1-0)/(NT-1))
        int          curWord = -1;
        unsigned int curVal  = 0u;

#pragma unroll 1
        for (int i = st; i < st + cnt; ++i) {
            float t = (i == NT - 1) ? 1.0f : __fmul_rn((float)i, dt);
            float u = __fadd_rn(1.0f, -t);
            float uu  = __fmul_rn(u, u);
            float ut2 = __fmul_rn(__fmul_rn(2.0f, u), t);
            float tt  = __fmul_rn(t, t);
            float X = __fadd_rn(__fadd_rn(__fmul_rn(uu, q0), __fmul_rn(ut2, q2)),
                                __fmul_rn(tt, q4));
            float Y = __fadd_rn(__fadd_rn(__fmul_rn(uu, q1), __fmul_rn(ut2, q3)),
                                __fmul_rn(tt, q5));
            int cx = (int)rintf(X);
            int cy = (int)rintf(Y);
            cx = min(max(cx, 0), HDIM - 1);
            cy = min(max(cy, 0), HDIM - 1);

            int          word = cx * HROW + (cy >> 1);
            unsigned int val  = 1u << ((cy & 1) * 16);
            if (word == curWord) {
                curVal += val;                 // merged: one atomic per run
            } else {
                if (curWord >= 0) atomicAdd(&Hp[curWord], curVal);
                curWord = word;
                curVal  = val;
            }
        }
        atomicAdd(&Hp[curWord], curVal);       // flush last run
    }
    __syncthreads();

    // ---- pass A (in place): y-window sums, one WARP per row ----
    // Lane l holds original words l and l+32 (and broadcast word 64).
    // Output word i packs py=2i (low) and py=2i+1 (high) window sums.
    {
        const int warp = tid >> 5;
        const int lane = tid & 31;
        for (int row = warp; row < HDIM; row += 8) {
            unsigned int* hr = Hp + row * HROW;
            unsigned int r0 = hr[lane];        // words 0..31 (conflict-free)
            unsigned int r1 = hr[32 + lane];   // words 32..63
            unsigned int r2 = hr[64];          // word 64 (h128|0), broadcast

            unsigned int lm  = __shfl_up_sync(0xffffffffu, r0, 1);   // w[l-1]
            unsigned int l31 = __shfl_sync(0xffffffffu, r0, 31);     // w[31]
            unsigned int m0  = __shfl_sync(0xffffffffu, r1, 0);      // w[32]
            unsigned int rp  = __shfl_down_sync(0xffffffffu, r0, 1); // w[l+1]
            unsigned int lm1 = __shfl_up_sync(0xffffffffu, r1, 1);   // w[l+31]
            unsigned int rp1 = __shfl_down_sync(0xffffffffu, r1, 1); // w[l+33]

            unsigned int wm  = (lane == 0)  ? (r0 << 16) : lm;  // i==0: pm = p0<<16
            unsigned int wp  = (lane == 31) ? m0  : rp;
            unsigned int wm1 = (lane == 0)  ? l31 : lm1;
            unsigned int wp1 = (lane == 31) ? r2  : rp1;

            // output word i = lane
            unsigned int a0w = __funnelshift_l(wm, r0, 16);   // (h[2i-1], h[2i])
            unsigned int c0w = __funnelshift_l(r0, wp, 16);   // (h[2i+1], h[2i+2])
            unsigned int o0  = a0w + r0 + c0w;

            // output word i = lane + 32
            unsigned int a1w = __funnelshift_l(wm1, r1, 16);
            unsigned int c1w = __funnelshift_l(r1, wp1, 16);
            unsigned int o1  = a1w + r1 + c1w;
            if (lane == 31) {
                // py=127 needs H126 + 2*H127 + 3*H128; sum gave H126+H127+H128
                unsigned int h127 = r1 >> 16;
                unsigned int h128 = wp1 & 0xffffu;
                o1 += (h127 + 2u * h128) << 16;
            }

            hr[lane]      = o0;   // conflict-free contiguous stores
            hr[32 + lane] = o1;
        }
    }
    __syncthreads();

    // ---- pass B: register-rolling x-window + inline clip + STG.128 ----
    // thread = (g, strip): g = column group (8 py), strip = 8 px rows
    float* dst = sketch + (size_t)b * (CAN * CAN);
    {
        const int g     = tid & 15;          // 0..15 -> py base 8g
        const int strip = tid >> 4;          // 0..15 -> px base 8*strip
        const int px0   = strip << 3;
        const unsigned int* gcol = Hp + (g << 2);

        uint4 ga, gb, gc;
        if (px0 == 0) {
            gb = *(const uint4*)&gcol[0];
            gc = *(const uint4*)&gcol[HROW];
            ga = gb;  // unused at px=0
        } else {
            ga = *(const uint4*)&gcol[(px0 - 1) * HROW];
            gb = *(const uint4*)&gcol[(px0    ) * HROW];
            gc = *(const uint4*)&gcol[(px0 + 1) * HROW];
        }

#pragma unroll
        for (int k = 0; k < 8; ++k) {
            int px = px0 + k;
            uint4 n4;
            if (px == 0) {
                n4.x = 2u * gb.x + gc.x;  n4.y = 2u * gb.y + gc.y;
                n4.z = 2u * gb.z + gc.z;  n4.w = 2u * gb.w + gc.w;
            } else if (px == CAN - 1) {
                n4.x = ga.x + 2u * gb.x + 3u * gc.x;
                n4.y = ga.y + 2u * gb.y + 3u * gc.y;
                n4.z = ga.z + 2u * gb.z + 3u * gc.z;
                n4.w = ga.w + 2u * gb.w + 3u * gc.w;
            } else {
                n4.x = ga.x + gb.x + gc.x;
                n4.y = ga.y + gb.y + gc.y;
                n4.z = ga.z + gb.z + gc.z;
                n4.w = ga.w + gb.w + gc.w;
            }

            unsigned int nn[8] = {
                n4.x & 0xffffu, n4.x >> 16, n4.y & 0xffffu, n4.y >> 16,
                n4.z & 0xffffu, n4.z >> 16, n4.w & 0xffffu, n4.w >> 16
            };
            float ov[8];
#pragma unroll
            for (int e = 0; e < 8; ++e) {
                unsigned int m = min(nn[e], 5u);   // clip saturates at n>=5
                float v = __fadd_rn(0.3f, __fmul_rn((float)m, -0.07f));
                ov[e] = fmaxf(v, 0.0f);
            }

            float* d = dst + px * CAN + (g << 3);
            ((float4*)d)[0] = make_float4(ov[0], ov[1], ov[2], ov[3]);
            ((float4*)d)[1] = make_float4(ov[4], ov[5], ov[6], ov[7]);

            // roll window
            ga = gb; gb = gc;
            if (k < 7) gc = *(const uint4*)&gcol[(px + 2) * HROW];
        }
    }
}

// ---------------------------------------------------------------------------
extern "C" void kernel_launch(void* const* d_in, const int* in_sizes, int n_in,
                              void* d_out, int out_size)
{
    const float* x    = (const float*)d_in[0];
    const float* W    = (const float*)d_in[1];
    const float* bv   = (const float*)d_in[2];
    float* out        = (float*)d_out;

    int B = in_sizes[0] / DIN;   // 2048

    cudaFuncSetAttribute(paint_kernel,
                         cudaFuncAttributeMaxDynamicSharedMemorySize,
                         SMEM_PAINT);

    agent_kernel<<<B / RPB, AGENT_THREADS>>>(x, W, bv, out, B);

    const float* sample = out + (size_t)B * (CAN * CAN) + 2 * (size_t)B;
    paint_kernel<<<B, 256, SMEM_PAINT>>>(sample, out);
}

// round 15
// speedup vs baseline: 1.0028x; 1.0028x over previous
#include <cuda_runtime.h>
#include <math.h>

// Problem constants
#define DIN   256      // agent input dim
#define C6    192      // S*6 = 32*6
#define CAN   128      // canvas size
#define NT    50       // samples per curve
#define NPTS  (32*NT)  // 1600 curve points per image
#define HDIM  129      // center coords are in [0,128]
#define HROW  68       // u32 words per H row (129 u16 slots, padded to 16B multiple)
#define HPWORDS (HDIM*HROW)   // 8772 (multiple of 4)
#define SMEM_PAINT (HPWORDS * 4)   // 35088 B -> 6 blocks/SM

// ---------------------------------------------------------------------------
// f32x2 packed helpers (bit-identical per-lane IEEE fp32 ops)
// ---------------------------------------------------------------------------
__device__ __forceinline__ void ffma2(unsigned long long& d,
                                      unsigned long long a,
                                      unsigned long long b) {
    asm("fma.rn.f32x2 %0, %1, %2, %0;" : "+l"(d) : "l"(a), "l"(b));
}
__device__ __forceinline__ void fadd2(unsigned long long& d,
                                      unsigned long long a) {
    asm("add.rn.f32x2 %0, %0, %1;" : "+l"(d) : "l"(a));
}
__device__ __forceinline__ unsigned long long pack2(float lo, float hi) {
    unsigned long long r;
    asm("mov.b64 %0, {%1, %2};" : "=l"(r) : "f"(lo), "f"(hi));
    return r;
}
__device__ __forceinline__ void unpack2(unsigned long long v, float& lo, float& hi) {
    asm("mov.b64 {%0, %1}, %2;" : "=f"(lo), "=f"(hi) : "l"(v));
}

// ---------------------------------------------------------------------------
// Kernel A: mu = x@W + b ; sample = sigmoid(mu).
// SINGLE-WAVE config: RPB=16 rows/block, grid = 2048/16 = 128 blocks <= 148
// SMs -> one wave, no ragged second wave. 768 threads = 48 column-quads x
// 8 rowpairs x 2 k-groups (KSPLIT=2: one reassociation point, like R7/R11).
// Thread: 4 consecutive cols (LDG.128 of W, batches of 8 in flight) x 2 rows
// (broadcast LDS.64 of x) over 128 k-steps. W traffic = 128 x 196KB = 25 MB.
// No prefetch double-buffer (R14 showed the register cost kills it).
// ---------------------------------------------------------------------------
#define RPB 16
#define AGENT_THREADS 768
#define KSPLIT 2
#define KCHUNK (DIN / KSPLIT)    // 128
#define XSTR 18                  // xs row stride in floats (even -> u64-aligned)

__global__ void __launch_bounds__(AGENT_THREADS) agent_kernel(
    const float* __restrict__ x,
    const float* __restrict__ W,
    const float* __restrict__ bvec,
    float* __restrict__ out,   // full output buffer
    int B)
{
    __shared__ float xs[DIN * XSTR];                     // [k][r], stride 18
    __shared__ unsigned long long part[384 * 4];         // g=1 partials, 12KB

    const int tid  = threadIdx.x;
    const int q    = tid % 48;            // column quad: cols 4q..4q+3
    const int p    = (tid / 48) & 7;      // rowpair: rows 2p, 2p+1 (0..7)
    const int g    = tid / 384;           // k-group: k in [128g, 128g+128)
    const int row0 = blockIdx.x * RPB;

    // Stage x tile transposed (coalesced gmem reads).
    for (int idx = tid; idx < RPB * DIN; idx += AGENT_THREADS) {
        int r = idx >> 8;        // 0..15
        int k = idx & 255;
        xs[k * XSTR + r] = x[(size_t)(row0 + r) * DIN + k];
    }
    __syncthreads();

    unsigned long long acc0, acc1, acc2, acc3;
    if (g == 0) {
        float4 b4 = *(const float4*)&bvec[q * 4];
        acc0 = pack2(b4.x, b4.x);
        acc1 = pack2(b4.y, b4.y);
        acc2 = pack2(b4.z, b4.z);
        acc3 = pack2(b4.w, b4.w);
    } else {
        acc0 = acc1 = acc2 = acc3 = 0ull;
    }

    const float4* Wq = (const float4*)(W + q * 4);   // row stride 48 float4s
    const float*  xp = &xs[p * 2];
    const int     kb = g * KCHUNK;

#pragma unroll 1
    for (int k0 = 0; k0 < KCHUNK; k0 += 8) {
        float4 wv[8];
#pragma unroll
        for (int u = 0; u < 8; ++u)
            wv[u] = __ldg(&Wq[(size_t)(kb + k0 + u) * 48]);  // 8 LDG.128 in flight
#pragma unroll
        for (int u = 0; u < 8; ++u) {
            unsigned long long v =
                *(const unsigned long long*)&xp[(kb + k0 + u) * XSTR];
            ffma2(acc0, v, pack2(wv[u].x, wv[u].x));
            ffma2(acc1, v, pack2(wv[u].y, wv[u].y));
            ffma2(acc2, v, pack2(wv[u].z, wv[u].z));
            ffma2(acc3, v, pack2(wv[u].w, wv[u].w));
        }
    }

    const int slot = (p * 48 + q) * 4;
    if (g == 1) {
        unsigned long long* pj = &part[slot];
        pj[0] = acc0; pj[1] = acc1; pj[2] = acc2; pj[3] = acc3;
    }
    __syncthreads();

    if (g == 0) {
        const unsigned long long* pj = &part[slot];
        fadd2(acc0, pj[0]);
        fadd2(acc1, pj[1]);
        fadd2(acc2, pj[2]);
        fadd2(acc3, pj[3]);

        // Output layout: [sketch B*128*128][log_prob B][entropy B][sample B*192]
        const size_t off_lp  = (size_t)B * (CAN * CAN);
        const size_t off_ent = off_lp + B;
        const size_t off_smp = off_ent + B;

        // log_prob / entropy are constants (raw == mu).
        const float logscale = logf(1e-4f);
        const float l2pi     = logf(6.2831855f);       // log(fl32(2*pi))
        const float lp  = 192.0f * (-logscale - 0.5f * l2pi);
        const float ent = 192.0f * (0.5f + 0.5f * l2pi + logscale);
        if (tid < RPB) {
            out[off_lp  + row0 + tid] = lp;
            out[off_ent + row0 + tid] = ent;
        }

        float m0x, m1x, m0y, m1y, m0z, m1z, m0w, m1w;
        unpack2(acc0, m0x, m1x);   // col 4q+0: rows 2p, 2p+1
        unpack2(acc1, m0y, m1y);
        unpack2(acc2, m0z, m1z);
        unpack2(acc3, m0w, m1w);

        float4 s0, s1;
        s0.x = 1.0f / (1.0f + expf(-m0x));
        s0.y = 1.0f / (1.0f + expf(-m0y));
        s0.z = 1.0f / (1.0f + expf(-m0z));
        s0.w = 1.0f / (1.0f + expf(-m0w));
        s1.x = 1.0f / (1.0f + expf(-m1x));
        s1.y = 1.0f / (1.0f + expf(-m1y));
        s1.z = 1.0f / (1.0f + expf(-m1z));
        s1.w = 1.0f / (1.0f + expf(-m1w));

        float* smp = out + off_smp;
        *(float4*)&smp[(size_t)(row0 + 2 * p    ) * C6 + q * 4] = s0;
        *(float4*)&smp[(size_t)(row0 + 2 * p + 1) * C6 + q * 4] = s1;
    }
}

// ---------------------------------------------------------------------------
// Kernel B: paint — EXACT R11 version (35.2 us proven).
//  1) histogram with run-length merged atomics (scalar __fmul_rn/__fadd_rn
//     curve eval, bit-identical to reference)
//  2) pass A (y-window): IN PLACE, one WARP per row, shuffles for neighbors
//  3) pass B (x-window): register-rolling over px, inline clip arithmetic
// Edge weights from clipping:  p=0 -> {2,1} on centers {0,1};
//                              p=127 -> {1,2,3} on centers {126,127,128}.
// All packed-u16 sums bounded by 14400 < 65536: no carry across halves.
// ---------------------------------------------------------------------------
__global__ void __launch_bounds__(256) paint_kernel(
    const float* __restrict__ sample,   // [B, 192]
    float* __restrict__ sketch)         // [B, 128, 128]
{
    extern __shared__ uint4 sh16[];       // 16B-aligned base
    unsigned int* Hp = (unsigned int*)sh16;   // [129][68] u32
    __shared__ float prm[C6];

    const int b   = blockIdx.x;
    const int tid = threadIdx.x;

    // zero Hp with 16B stores
    {
        uint4 z = make_uint4(0u, 0u, 0u, 0u);
        uint4* hp4 = (uint4*)Hp;
        for (int i = tid; i < HPWORDS / 4; i += 256) hp4[i] = z;
    }
    if (tid < C6) prm[tid] = __fmul_rn(sample[(size_t)b * C6 + tid], 128.0f);
    __syncthreads();

    // ---- histogram: run-length merged atomics ----
    // thread = (spline s = tid>>3, chunk sub = tid&7); sample counts
    // {7,7,6,6,6,6,6,6} -> start 0,7,14,20,26,32,38,44.
    {
        const int s    = tid >> 3;
        const int sub  = tid & 7;
        const int st   = (sub < 2) ? 7 * sub : 14 + 6 * (sub - 2);
        const int cnt  = (sub < 2) ? 7 : 6;

        const float q0 = prm[s * 6 + 0];
        const float q1 = prm[s * 6 + 1];
        const float q2 = prm[s * 6 + 2];
        const float q3 = prm[s * 6 + 3];
        const float q4 = prm[s * 6 + 4];
        const float q5 = prm[s * 6 + 5];

        const float dt = 1.0f / 49.0f;   // fl32((1-0)/(NT-1))
        int          curWord = -1;
        unsigned int curVal  = 0u;

#pragma unroll 1
        for (int i = st; i < st + cnt; ++i) {
            float t = (i == NT - 1) ? 1.0f : __fmul_rn((float)i, dt);
            float u = __fadd_rn(1.0f, -t);
            float uu  = __fmul_rn(u, u);
            float ut2 = __fmul_rn(__fmul_rn(2.0f, u), t);
            float tt  = __fmul_rn(t, t);
            float X = __fadd_rn(__fadd_rn(__fmul_rn(uu, q0), __fmul_rn(ut2, q2)),
                                __fmul_rn(tt, q4));
            float Y = __fadd_rn(__fadd_rn(__fmul_rn(uu, q1), __fmul_rn(ut2, q3)),
                                __fmul_rn(tt, q5));
            int cx = (int)rintf(X);
            int cy = (int)rintf(Y);
            cx = min(max(cx, 0), HDIM - 1);
            cy = min(max(cy, 0), HDIM - 1);

            int          word = cx * HROW + (cy >> 1);
            unsigned int val  = 1u << ((cy & 1) * 16);
            if (word == curWord) {
                curVal += val;                 // merged: one atomic per run
            } else {
                if (curWord >= 0) atomicAdd(&Hp[curWord], curVal);
                curWord = word;
                curVal  = val;
            }
        }
        atomicAdd(&Hp[curWord], curVal);       // flush last run
    }
    __syncthreads();

    // ---- pass A (in place): y-window sums, one WARP per row ----
    // Lane l holds original words l and l+32 (and broadcast word 64).
    // Output word i packs py=2i (low) and py=2i+1 (high) window sums.
    {
        const int warp = tid >> 5;
        const int lane = tid & 31;
        for (int row = warp; row < HDIM; row += 8) {
            unsigned int* hr = Hp + row * HROW;
            unsigned int r0 = hr[lane];        // words 0..31 (conflict-free)
            unsigned int r1 = hr[32 + lane];   // words 32..63
            unsigned int r2 = hr[64];          // word 64 (h128|0), broadcast

            unsigned int lm  = __shfl_up_sync(0xffffffffu, r0, 1);   // w[l-1]
            unsigned int l31 = __shfl_sync(0xffffffffu, r0, 31);     // w[31]
            unsigned int m0  = __shfl_sync(0xffffffffu, r1, 0);      // w[32]
            unsigned int rp  = __shfl_down_sync(0xffffffffu, r0, 1); // w[l+1]
            unsigned int lm1 = __shfl_up_sync(0xffffffffu, r1, 1);   // w[l+31]
            unsigned int rp1 = __shfl_down_sync(0xffffffffu, r1, 1); // w[l+33]

            unsigned int wm  = (lane == 0)  ? (r0 << 16) : lm;  // i==0: pm = p0<<16
            unsigned int wp  = (lane == 31) ? m0  : rp;
            unsigned int wm1 = (lane == 0)  ? l31 : lm1;
            unsigned int wp1 = (lane == 31) ? r2  : rp1;

            // output word i = lane
            unsigned int a0w = __funnelshift_l(wm, r0, 16);   // (h[2i-1], h[2i])
            unsigned int c0w = __funnelshift_l(r0, wp, 16);   // (h[2i+1], h[2i+2])
            unsigned int o0  = a0w + r0 + c0w;

            // output word i = lane + 32
            unsigned int a1w = __funnelshift_l(wm1, r1, 16);
            unsigned int c1w = __funnelshift_l(r1, wp1, 16);
            unsigned int o1  = a1w + r1 + c1w;
            if (lane == 31) {
                // py=127 needs H126 + 2*H127 + 3*H128; sum gave H126+H127+H128
                unsigned int h127 = r1 >> 16;
                unsigned int h128 = wp1 & 0xffffu;
                o1 += (h127 + 2u * h128) << 16;
            }

            hr[lane]      = o0;   // conflict-free contiguous stores
            hr[32 + lane] = o1;
        }
    }
    __syncthreads();

    // ---- pass B: register-rolling x-window + inline clip + STG.128 ----
    // thread = (g, strip): g = column group (8 py), strip = 8 px rows
    float* dst = sketch + (size_t)b * (CAN * CAN);
    {
        const int g     = tid & 15;          // 0..15 -> py base 8g
        const int strip = tid >> 4;          // 0..15 -> px base 8*strip
        const int px0   = strip << 3;
        const unsigned int* gcol = Hp + (g << 2);

        uint4 ga, gb, gc;
        if (px0 == 0) {
            gb = *(const uint4*)&gcol[0];
            gc = *(const uint4*)&gcol[HROW];
            ga = gb;  // unused at px=0
        } else {
            ga = *(const uint4*)&gcol[(px0 - 1) * HROW];
            gb = *(const uint4*)&gcol[(px0    ) * HROW];
            gc = *(const uint4*)&gcol[(px0 + 1) * HROW];
        }

#pragma unroll
        for (int k = 0; k < 8; ++k) {
            int px = px0 + k;
            uint4 n4;
            if (px == 0) {
                n4.x = 2u * gb.x + gc.x;  n4.y = 2u * gb.y + gc.y;
                n4.z = 2u * gb.z + gc.z;  n4.w = 2u * gb.w + gc.w;
            } else if (px == CAN - 1) {
                n4.x = ga.x + 2u * gb.x + 3u * gc.x;
                n4.y = ga.y + 2u * gb.y + 3u * gc.y;
                n4.z = ga.z + 2u * gb.z + 3u * gc.z;
                n4.w = ga.w + 2u * gb.w + 3u * gc.w;
            } else {
                n4.x = ga.x + gb.x + gc.x;
                n4.y = ga.y + gb.y + gc.y;
                n4.z = ga.z + gb.z + gc.z;
                n4.w = ga.w + gb.w + gc.w;
            }

            unsigned int nn[8] = {
                n4.x & 0xffffu, n4.x >> 16, n4.y & 0xffffu, n4.y >> 16,
                n4.z & 0xffffu, n4.z >> 16, n4.w & 0xffffu, n4.w >> 16
            };
            float ov[8];
#pragma unroll
            for (int e = 0; e < 8; ++e) {
                unsigned int m = min(nn[e], 5u);   // clip saturates at n>=5
                float v = __fadd_rn(0.3f, __fmul_rn((float)m, -0.07f));
                ov[e] = fmaxf(v, 0.0f);
            }

            float* d = dst + px * CAN + (g << 3);
            ((float4*)d)[0] = make_float4(ov[0], ov[1], ov[2], ov[3]);
            ((float4*)d)[1] = make_float4(ov[4], ov[5], ov[6], ov[7]);

            // roll window
            ga = gb; gb = gc;
            if (k < 7) gc = *(const uint4*)&gcol[(px + 2) * HROW];
        }
    }
}

// ---------------------------------------------------------------------------
extern "C" void kernel_launch(void* const* d_in, const int* in_sizes, int n_in,
                              void* d_out, int out_size)
{
    const float* x    = (const float*)d_in[0];
    const float* W    = (const float*)d_in[1];
    const float* bv   = (const float*)d_in[2];
    float* out        = (float*)d_out;

    int B = in_sizes[0] / DIN;   // 2048

    cudaFuncSetAttribute(paint_kernel,
                         cudaFuncAttributeMaxDynamicSharedMemorySize,
                         SMEM_PAINT);

    agent_kernel<<<B / RPB, AGENT_THREADS>>>(x, W, bv, out, B);

    const float* sample = out + (size_t)B * (CAN * CAN) + 2 * (size_t)B;
    paint_kernel<<<B, 256, SMEM_PAINT>>>(sample, out);
}

// round 16
// speedup vs baseline: 1.2164x; 1.2130x over previous
#include <cuda_runtime.h>
#include <math.h>

// Problem constants
#define DIN   256      // agent input dim
#define C6    192      // S*6 = 32*6
#define CAN   128      // canvas size
#define NT    50       // samples per curve
#define NPTS  (32*NT)  // 1600 curve points per image
#define HDIM  129      // center coords are in [0,128]
#define HROW  68       // u32 words per H row (129 u16 slots, padded to 16B multiple)
#define HPWORDS (HDIM*HROW)   // 8772 (multiple of 4)
#define SMEM_PAINT (HPWORDS * 4)   // 35088 B -> 6 blocks/SM

// ---------------------------------------------------------------------------
// f32x2 packed helpers (bit-identical per-lane IEEE fp32 ops)
// ---------------------------------------------------------------------------
__device__ __forceinline__ void ffma2(unsigned long long& d,
                                      unsigned long long a,
                                      unsigned long long b) {
    asm("fma.rn.f32x2 %0, %1, %2, %0;" : "+l"(d) : "l"(a), "l"(b));
}
__device__ __forceinline__ void fadd2(unsigned long long& d,
                                      unsigned long long a) {
    asm("add.rn.f32x2 %0, %0, %1;" : "+l"(d) : "l"(a));
}
__device__ __forceinline__ unsigned long long pack2(float lo, float hi) {
    unsigned long long r;
    asm("mov.b64 %0, {%1, %2};" : "=l"(r) : "f"(lo), "f"(hi));
    return r;
}
__device__ __forceinline__ void unpack2(unsigned long long v, float& lo, float& hi) {
    asm("mov.b64 {%0, %1}, %2;" : "=f"(lo), "=f"(hi) : "l"(v));
}

// ---------------------------------------------------------------------------
// Kernel A: EXACT R11 agent (proven 14.4 us incl. gap).
// 768 threads = 48 column-quads x 4 rowpairs x 4 k-groups; RPB=8, grid 256.
// ---------------------------------------------------------------------------
#define RPB 8
#define AGENT_THREADS 768
#define KSPLIT 4
#define KCHUNK (DIN / KSPLIT)    // 64
#define XSTR 10                  // xs row stride in floats (even -> u64-aligned)

__global__ void __launch_bounds__(AGENT_THREADS) agent_kernel(
    const float* __restrict__ x,
    const float* __restrict__ W,
    const float* __restrict__ bvec,
    float* __restrict__ out,   // full output buffer
    int B)
{
    __shared__ float xs[DIN * XSTR];                     // [k][r], stride 10
    __shared__ unsigned long long part[C6 * (KSPLIT-1) * 4]; // 2304 u64 = 18KB

    const int tid  = threadIdx.x;
    const int q    = tid % 48;            // column quad: cols 4q..4q+3
    const int p    = (tid / 48) & 3;      // rowpair: rows 2p, 2p+1
    const int g    = tid / 192;           // k-group: k in [64g, 64g+64)
    const int row0 = blockIdx.x * RPB;

    for (int idx = tid; idx < RPB * DIN; idx += AGENT_THREADS) {
        int r = idx >> 8;        // 0..7
        int k = idx & 255;
        xs[k * XSTR + r] = x[(size_t)(row0 + r) * DIN + k];
    }
    __syncthreads();

    unsigned long long acc0, acc1, acc2, acc3;
    if (g == 0) {
        float4 b4 = *(const float4*)&bvec[q * 4];
        acc0 = pack2(b4.x, b4.x);
        acc1 = pack2(b4.y, b4.y);
        acc2 = pack2(b4.z, b4.z);
        acc3 = pack2(b4.w, b4.w);
    } else {
        acc0 = acc1 = acc2 = acc3 = 0ull;
    }

    const float4* Wq = (const float4*)(W + q * 4);   // row stride 48 float4s
    const float*  xp = &xs[p * 2];
    const int     kb = g * KCHUNK;

#pragma unroll 1
    for (int k0 = 0; k0 < KCHUNK; k0 += 8) {
        float4 wv[8];
#pragma unroll
        for (int u = 0; u < 8; ++u)
            wv[u] = __ldg(&Wq[(size_t)(kb + k0 + u) * 48]);  // 8 LDG.128 in flight
#pragma unroll
        for (int u = 0; u < 8; ++u) {
            unsigned long long v =
                *(const unsigned long long*)&xp[(kb + k0 + u) * XSTR];
            ffma2(acc0, v, pack2(wv[u].x, wv[u].x));
            ffma2(acc1, v, pack2(wv[u].y, wv[u].y));
            ffma2(acc2, v, pack2(wv[u].z, wv[u].z));
            ffma2(acc3, v, pack2(wv[u].w, wv[u].w));
        }
    }

    const int slot = (p * 48 + q) * ((KSPLIT - 1) * 4);
    if (g > 0) {
        unsigned long long* pj = &part[slot + (g - 1) * 4];
        pj[0] = acc0; pj[1] = acc1; pj[2] = acc2; pj[3] = acc3;
    }
    __syncthreads();

    if (g == 0) {
        const unsigned long long* pj = &part[slot];
#pragma unroll
        for (int gg = 0; gg < KSPLIT - 1; ++gg) {
            fadd2(acc0, pj[gg * 4 + 0]);
            fadd2(acc1, pj[gg * 4 + 1]);
            fadd2(acc2, pj[gg * 4 + 2]);
            fadd2(acc3, pj[gg * 4 + 3]);
        }

        // Output layout: [sketch B*128*128][log_prob B][entropy B][sample B*192]
        const size_t off_lp  = (size_t)B * (CAN * CAN);
        const size_t off_ent = off_lp + B;
        const size_t off_smp = off_ent + B;

        // log_prob / entropy are constants (raw == mu).
        const float logscale = logf(1e-4f);
        const float l2pi     = logf(6.2831855f);       // log(fl32(2*pi))
        const float lp  = 192.0f * (-logscale - 0.5f * l2pi);
        const float ent = 192.0f * (0.5f + 0.5f * l2pi + logscale);
        if (tid < RPB) {
            out[off_lp  + row0 + tid] = lp;
            out[off_ent + row0 + tid] = ent;
        }

        float m0x, m1x, m0y, m1y, m0z, m1z, m0w, m1w;
        unpack2(acc0, m0x, m1x);   // col 4q+0: rows 2p, 2p+1
        unpack2(acc1, m0y, m1y);
        unpack2(acc2, m0z, m1z);
        unpack2(acc3, m0w, m1w);

        float4 s0, s1;
        s0.x = 1.0f / (1.0f + expf(-m0x));
        s0.y = 1.0f / (1.0f + expf(-m0y));
        s0.z = 1.0f / (1.0f + expf(-m0z));
        s0.w = 1.0f / (1.0f + expf(-m0w));
        s1.x = 1.0f / (1.0f + expf(-m1x));
        s1.y = 1.0f / (1.0f + expf(-m1y));
        s1.z = 1.0f / (1.0f + expf(-m1z));
        s1.w = 1.0f / (1.0f + expf(-m1w));

        float* smp = out + off_smp;
        *(float4*)&smp[(size_t)(row0 + 2 * p    ) * C6 + q * 4] = s0;
        *(float4*)&smp[(size_t)(row0 + 2 * p + 1) * C6 + q * 4] = s1;
    }
}

// ---------------------------------------------------------------------------
// Kernel B: paint = R11 + CONVEX-HULL ROW CULLING.
// A quadratic Bezier lies in the convex hull of its control points, so every
// curve x lies in [min,max] of the 96 x-control values (prm indices 0,2,4
// mod 6). With +/-1 margin for fp rounding, rows outside [cxlo,cxhi] are
// provably untouched: passA skips them (they are already all-zero = correct
// windowed output) and passB strips with no window overlap emit constant
// background 0.3 and skip all shared loads / sums.
//  1) histogram with run-length merged atomics (bit-identical eval)
//  2) pass A (y-window): IN PLACE, one WARP per occupied row
//  3) pass B (x-window): register-rolling over px, inline clip; hull-culled
// ---------------------------------------------------------------------------
__global__ void __launch_bounds__(256) paint_kernel(
    const float* __restrict__ sample,   // [B, 192]
    float* __restrict__ sketch)         // [B, 128, 128]
{
    extern __shared__ uint4 sh16[];       // 16B-aligned base
    unsigned int* Hp = (unsigned int*)sh16;   // [129][68] u32
    __shared__ float prm[C6];
    __shared__ int cxmm[2];               // {min, max} of rint(x-controls)

    const int b   = blockIdx.x;
    const int tid = threadIdx.x;

    // zero Hp with 16B stores
    {
        uint4 z = make_uint4(0u, 0u, 0u, 0u);
        uint4* hp4 = (uint4*)Hp;
        for (int i = tid; i < HPWORDS / 4; i += 256) hp4[i] = z;
    }
    if (tid < C6) prm[tid] = __fmul_rn(sample[(size_t)b * C6 + tid], 128.0f);
    if (tid == 255) { cxmm[0] = 0x7fffffff; cxmm[1] = -0x7fffffff; }
    __syncthreads();

    // hull bounds over the 96 x-control values (prm[6s+0], [6s+2], [6s+4])
    if (tid < 96) {
        int s = tid / 3, e = tid - 3 * s;
        float v = prm[s * 6 + e * 2];
        int r = (int)rintf(v);
        atomicMin(&cxmm[0], r);
        atomicMax(&cxmm[1], r);
    }

    // ---- histogram: run-length merged atomics ----
    // thread = (spline s = tid>>3, chunk sub = tid&7); sample counts
    // {7,7,6,6,6,6,6,6} -> start 0,7,14,20,26,32,38,44.
    {
        const int s    = tid >> 3;
        const int sub  = tid & 7;
        const int st   = (sub < 2) ? 7 * sub : 14 + 6 * (sub - 2);
        const int cnt  = (sub < 2) ? 7 : 6;

        const float q0 = prm[s * 6 + 0];
        const float q1 = prm[s * 6 + 1];
        const float q2 = prm[s * 6 + 2];
        const float q3 = prm[s * 6 + 3];
        const float q4 = prm[s * 6 + 4];
        const float q5 = prm[s * 6 + 5];

        const float dt = 1.0f / 49.0f;   // fl32((1-0)/(NT-1))
        int          curWord = -1;
        unsigned int curVal  = 0u;

#pragma unroll 1
        for (int i = st; i < st + cnt; ++i) {
            float t = (i == NT - 1) ? 1.0f : __fmul_rn((float)i, dt);
            float u = __fadd_rn(1.0f, -t);
            float uu  = __fmul_rn(u, u);
            float ut2 = __fmul_rn(__fmul_rn(2.0f, u), t);
            float tt  = __fmul_rn(t, t);
            float X = __fadd_rn(__fadd_rn(__fmul_rn(uu, q0), __fmul_rn(ut2, q2)),
                                __fmul_rn(tt, q4));
            float Y = __fadd_rn(__fadd_rn(__fmul_rn(uu, q1), __fmul_rn(ut2, q3)),
                                __fmul_rn(tt, q5));
            int cx = (int)rintf(X);
            int cy = (int)rintf(Y);
            cx = min(max(cx, 0), HDIM - 1);
            cy = min(max(cy, 0), HDIM - 1);

            int          word = cx * HROW + (cy >> 1);
            unsigned int val  = 1u << ((cy & 1) * 16);
            if (word == curWord) {
                curVal += val;                 // merged: one atomic per run
            } else {
                if (curWord >= 0) atomicAdd(&Hp[curWord], curVal);
                curWord = word;
                curVal  = val;
            }
        }
        atomicAdd(&Hp[curWord], curVal);       // flush last run
    }
    __syncthreads();

    // hull row bounds with fp-safety margin, clipped like cx itself
    const int cxlo = max(0,        cxmm[0] - 1);
    const int cxhi = min(HDIM - 1, cxmm[1] + 1);

    // ---- pass A (in place): y-window sums, one WARP per OCCUPIED row ----
    // Rows outside [cxlo,cxhi] are untouched zeros = correct window output.
    {
        const int warp = tid >> 5;
        const int lane = tid & 31;
        for (int row = cxlo + warp; row <= cxhi; row += 8) {
            unsigned int* hr = Hp + row * HROW;
            unsigned int r0 = hr[lane];        // words 0..31 (conflict-free)
            unsigned int r1 = hr[32 + lane];   // words 32..63
            unsigned int r2 = hr[64];          // word 64 (h128|0), broadcast

            unsigned int lm  = __shfl_up_sync(0xffffffffu, r0, 1);   // w[l-1]
            unsigned int l31 = __shfl_sync(0xffffffffu, r0, 31);     // w[31]
            unsigned int m0  = __shfl_sync(0xffffffffu, r1, 0);      // w[32]
            unsigned int rp  = __shfl_down_sync(0xffffffffu, r0, 1); // w[l+1]
            unsigned int lm1 = __shfl_up_sync(0xffffffffu, r1, 1);   // w[l+31]
            unsigned int rp1 = __shfl_down_sync(0xffffffffu, r1, 1); // w[l+33]

            unsigned int wm  = (lane == 0)  ? (r0 << 16) : lm;  // i==0: pm = p0<<16
            unsigned int wp  = (lane == 31) ? m0  : rp;
            unsigned int wm1 = (lane == 0)  ? l31 : lm1;
            unsigned int wp1 = (lane == 31) ? r2  : rp1;

            // output word i = lane
            unsigned int a0w = __funnelshift_l(wm, r0, 16);   // (h[2i-1], h[2i])
            unsigned int c0w = __funnelshift_l(r0, wp, 16);   // (h[2i+1], h[2i+2])
            unsigned int o0  = a0w + r0 + c0w;

            // output word i = lane + 32
            unsigned int a1w = __funnelshift_l(wm1, r1, 16);
            unsigned int c1w = __funnelshift_l(r1, wp1, 16);
            unsigned int o1  = a1w + r1 + c1w;
            if (lane == 31) {
                // py=127 needs H126 + 2*H127 + 3*H128; sum gave H126+H127+H128
                unsigned int h127 = r1 >> 16;
                unsigned int h128 = wp1 & 0xffffu;
                o1 += (h127 + 2u * h128) << 16;
            }

            hr[lane]      = o0;   // conflict-free contiguous stores
            hr[32 + lane] = o1;
        }
    }
    __syncthreads();

    // ---- pass B: register-rolling x-window + inline clip + STG.128 ----
    // thread = (g, strip): g = column group (8 py), strip = 8 px rows.
    // Strips whose window [px0-1, px0+8] misses [cxlo,cxhi] are pure
    // background: constant stores, no shared loads.
    float* dst = sketch + (size_t)b * (CAN * CAN);
    {
        const int g     = tid & 15;          // 0..15 -> py base 8g
        const int strip = tid >> 4;          // 0..15 -> px base 8*strip
        const int px0   = strip << 3;

        if (cxhi < px0 - 1 || cxlo > px0 + 8) {
            const float4 bg = make_float4(0.3f, 0.3f, 0.3f, 0.3f);
            float* d = dst + px0 * CAN + (g << 3);
#pragma unroll
            for (int k = 0; k < 8; ++k) {
                ((float4*)(d + k * CAN))[0] = bg;
                ((float4*)(d + k * CAN))[1] = bg;
            }
        } else {
            const unsigned int* gcol = Hp + (g << 2);

            uint4 ga, gb, gc;
            if (px0 == 0) {
                gb = *(const uint4*)&gcol[0];
                gc = *(const uint4*)&gcol[HROW];
                ga = gb;  // unused at px=0
            } else {
                ga = *(const uint4*)&gcol[(px0 - 1) * HROW];
                gb = *(const uint4*)&gcol[(px0    ) * HROW];
                gc = *(const uint4*)&gcol[(px0 + 1) * HROW];
            }

#pragma unroll
            for (int k = 0; k < 8; ++k) {
                int px = px0 + k;
                uint4 n4;
                if (px == 0) {
                    n4.x = 2u * gb.x + gc.x;  n4.y = 2u * gb.y + gc.y;
                    n4.z = 2u * gb.z + gc.z;  n4.w = 2u * gb.w + gc.w;
                } else if (px == CAN - 1) {
                    n4.x = ga.x + 2u * gb.x + 3u * gc.x;
                    n4.y = ga.y + 2u * gb.y + 3u * gc.y;
                    n4.z = ga.z + 2u * gb.z + 3u * gc.z;
                    n4.w = ga.w + 2u * gb.w + 3u * gc.w;
                } else {
                    n4.x = ga.x + gb.x + gc.x;
                    n4.y = ga.y + gb.y + gc.y;
                    n4.z = ga.z + gb.z + gc.z;
                    n4.w = ga.w + gb.w + gc.w;
                }

                unsigned int nn[8] = {
                    n4.x & 0xffffu, n4.x >> 16, n4.y & 0xffffu, n4.y >> 16,
                    n4.z & 0xffffu, n4.z >> 16, n4.w & 0xffffu, n4.w >> 16
                };
                float ov[8];
#pragma unroll
                for (int e = 0; e < 8; ++e) {
                    unsigned int m = min(nn[e], 5u);   // clip saturates at n>=5
                    float v = __fadd_rn(0.3f, __fmul_rn((float)m, -0.07f));
                    ov[e] = fmaxf(v, 0.0f);
                }

                float* d = dst + px * CAN + (g << 3);
                ((float4*)d)[0] = make_float4(ov[0], ov[1], ov[2], ov[3]);
                ((float4*)d)[1] = make_float4(ov[4], ov[5], ov[6], ov[7]);

                // roll window
                ga = gb; gb = gc;
                if (k < 7) gc = *(const uint4*)&gcol[(px + 2) * HROW];
            }
        }
    }
}

// ---------------------------------------------------------------------------
extern "C" void kernel_launch(void* const* d_in, const int* in_sizes, int n_in,
                              void* d_out, int out_size)
{
    const float* x    = (const float*)d_in[0];
    const float* W    = (const float*)d_in[1];
    const float* bv   = (const float*)d_in[2];
    float* out        = (float*)d_out;

    int B = in_sizes[0] / DIN;   // 2048

    cudaFuncSetAttribute(paint_kernel,
                         cudaFuncAttributeMaxDynamicSharedMemorySize,
                         SMEM_PAINT);

    agent_kernel<<<B / RPB, AGENT_THREADS>>>(x, W, bv, out, B);

    const float* sample = out + (size_t)B * (CAN * CAN) + 2 * (size_t)B;
    paint_kernel<<<B, 256, SMEM_PAINT>>>(sample, out);
}